// round 2
// baseline (speedup 1.0000x reference)
#include <cuda_runtime.h>
#include <math.h>

#define N_BATCH 32
#define C_IN    256
#define C_SQ    64
#define HW      12544          // 112*112
#define HW4     3136           // HW/4
#define PLANES  (N_BATCH * C_IN)   // 8192

// Scratch (no allocations allowed)
__device__ float g_pool[PLANES];
__device__ float g_gate[PLANES];

// ---------------------------------------------------------------------------
// Kernel 1: global average pool. One block per (n,c) plane, float4 loads.
// ---------------------------------------------------------------------------
__global__ __launch_bounds__(256) void se_pool_kernel(
    const float* __restrict__ x)
{
    const int plane = blockIdx.x;
    const float4* p = reinterpret_cast<const float4*>(x + (size_t)plane * HW);

    float sum = 0.0f;
    #pragma unroll 4
    for (int i = threadIdx.x; i < HW4; i += 256) {
        float4 v = p[i];
        sum += (v.x + v.y) + (v.z + v.w);
    }

    // warp reduce
    #pragma unroll
    for (int off = 16; off > 0; off >>= 1)
        sum += __shfl_down_sync(0xFFFFFFFFu, sum, off);

    __shared__ float warp_sums[8];
    const int lane = threadIdx.x & 31;
    const int wid  = threadIdx.x >> 5;
    if (lane == 0) warp_sums[wid] = sum;
    __syncthreads();

    if (wid == 0) {
        float s = (lane < 8) ? warp_sums[lane] : 0.0f;
        #pragma unroll
        for (int off = 4; off > 0; off >>= 1)
            s += __shfl_down_sync(0xFFFFFFFFu, s, off);
        if (lane == 0)
            g_pool[plane] = s * (1.0f / (float)HW);
    }
}

// ---------------------------------------------------------------------------
// Kernel 2: MLP  s -> relu(W_r s + b_r) -> sigmoid(W_e . + b_e) -> gate
// One block per batch element, 256 threads (one per output channel).
// ---------------------------------------------------------------------------
__global__ __launch_bounds__(256) void se_mlp_kernel(
    const float* __restrict__ w_reduce,   // [C_SQ, C_IN]
    const float* __restrict__ b_reduce,   // [C_SQ]
    const float* __restrict__ w_expand,   // [C_IN, C_SQ]
    const float* __restrict__ b_expand)   // [C_IN]
{
    const int n   = blockIdx.x;
    const int tid = threadIdx.x;

    __shared__ float s_in[C_IN];
    __shared__ float s_red[C_SQ];

    s_in[tid] = g_pool[n * C_IN + tid];
    __syncthreads();

    if (tid < C_SQ) {
        float acc = b_reduce[tid];
        const float* wr = w_reduce + tid * C_IN;
        #pragma unroll 8
        for (int c = 0; c < C_IN; c++)
            acc = fmaf(wr[c], s_in[c], acc);
        s_red[tid] = fmaxf(acc, 0.0f);
    }
    __syncthreads();

    float acc = b_expand[tid];
    const float* we = w_expand + tid * C_SQ;
    #pragma unroll 8
    for (int k = 0; k < C_SQ; k++)
        acc = fmaf(we[k], s_red[k], acc);

    g_gate[n * C_IN + tid] = 1.0f / (1.0f + __expf(-acc));
}

// ---------------------------------------------------------------------------
// Kernel 3: out = gate[plane] * x, vectorized float4 (HW % 4 == 0 so every
// float4 is within a single plane).
// ---------------------------------------------------------------------------
__global__ __launch_bounds__(256) void se_scale_kernel(
    const float* __restrict__ x,
    float* __restrict__ out)
{
    const unsigned idx4 = blockIdx.x * 256u + threadIdx.x;   // float4 index
    const unsigned plane = idx4 / HW4;
    const float g = __ldg(&g_gate[plane]);

    float4 v = reinterpret_cast<const float4*>(x)[idx4];
    v.x *= g; v.y *= g; v.z *= g; v.w *= g;
    reinterpret_cast<float4*>(out)[idx4] = v;
}

// ---------------------------------------------------------------------------
extern "C" void kernel_launch(void* const* d_in, const int* in_sizes, int n_in,
                              void* d_out, int out_size)
{
    const float* x        = (const float*)d_in[0];
    const float* w_reduce = (const float*)d_in[1];
    const float* b_reduce = (const float*)d_in[2];
    const float* w_expand = (const float*)d_in[3];
    const float* b_expand = (const float*)d_in[4];
    float* out = (float*)d_out;

    // Pass 1: pool
    se_pool_kernel<<<PLANES, 256>>>(x);

    // Pass 2: tiny MLP -> gate
    se_mlp_kernel<<<N_BATCH, 256>>>(w_reduce, b_reduce, w_expand, b_expand);

    // Pass 3: scale
    const unsigned total4 = (unsigned)((size_t)PLANES * HW4);   // 25,690,112
    se_scale_kernel<<<total4 / 256, 256>>>(x, out);
}

// round 3
// speedup vs baseline: 1.0346x; 1.0346x over previous
#include <cuda_runtime.h>
#include <math.h>

#define N_BATCH 32
#define C_IN    256
#define C_SQ    64
#define HW      12544              // 112*112
#define HW4     3136               // HW/4 float4 per plane
#define PLANES  (N_BATCH * C_IN)   // 8192
#define TPB     448                // 448 * 7 == 3136 exactly
#define VPT     7                  // float4 per thread

// Scratch (no allocations allowed)
__device__ float g_pool[PLANES];
__device__ float g_gate[PLANES];

// ---------------------------------------------------------------------------
// Kernel 1: global average pool. One block per (n,c) plane.
// 448 threads x 7 float4 each = 3136 float4 = whole plane, fully unrolled.
// ---------------------------------------------------------------------------
__global__ __launch_bounds__(TPB) void se_pool_kernel(
    const float* __restrict__ x)
{
    const int plane = blockIdx.x;
    const float4* p = reinterpret_cast<const float4*>(x + (size_t)plane * HW);

    float4 v[VPT];
    #pragma unroll
    for (int i = 0; i < VPT; i++)
        v[i] = __ldcs(&p[threadIdx.x + i * TPB]);

    float sum = 0.0f;
    #pragma unroll
    for (int i = 0; i < VPT; i++)
        sum += (v[i].x + v[i].y) + (v[i].z + v[i].w);

    // warp reduce
    #pragma unroll
    for (int off = 16; off > 0; off >>= 1)
        sum += __shfl_down_sync(0xFFFFFFFFu, sum, off);

    __shared__ float warp_sums[TPB / 32];   // 14 warps
    const int lane = threadIdx.x & 31;
    const int wid  = threadIdx.x >> 5;
    if (lane == 0) warp_sums[wid] = sum;
    __syncthreads();

    if (wid == 0) {
        float s = (lane < TPB / 32) ? warp_sums[lane] : 0.0f;
        #pragma unroll
        for (int off = 8; off > 0; off >>= 1)
            s += __shfl_down_sync(0xFFFFFFFFu, s, off);
        if (lane == 0)
            g_pool[plane] = s * (1.0f / (float)HW);
    }
}

// ---------------------------------------------------------------------------
// Kernel 2: MLP  s -> relu(W_r s + b_r) -> sigmoid(W_e . + b_e) -> gate
// One block per batch element, 256 threads (one per output channel).
// ---------------------------------------------------------------------------
__global__ __launch_bounds__(256) void se_mlp_kernel(
    const float* __restrict__ w_reduce,   // [C_SQ, C_IN]
    const float* __restrict__ b_reduce,   // [C_SQ]
    const float* __restrict__ w_expand,   // [C_IN, C_SQ]
    const float* __restrict__ b_expand)   // [C_IN]
{
    const int n   = blockIdx.x;
    const int tid = threadIdx.x;

    __shared__ float s_in[C_IN];
    __shared__ float s_red[C_SQ];

    s_in[tid] = g_pool[n * C_IN + tid];
    __syncthreads();

    if (tid < C_SQ) {
        float acc = b_reduce[tid];
        const float* wr = w_reduce + tid * C_IN;
        #pragma unroll 8
        for (int c = 0; c < C_IN; c++)
            acc = fmaf(wr[c], s_in[c], acc);
        s_red[tid] = fmaxf(acc, 0.0f);
    }
    __syncthreads();

    float acc = b_expand[tid];
    const float* we = w_expand + tid * C_SQ;
    #pragma unroll 8
    for (int k = 0; k < C_SQ; k++)
        acc = fmaf(we[k], s_red[k], acc);

    g_gate[n * C_IN + tid] = 1.0f / (1.0f + __expf(-acc));
}

// ---------------------------------------------------------------------------
// Kernel 3: out = gate[plane] * x. One block per plane, 448 threads x 7
// float4 each, fully unrolled: loads front-batched (MLP=7), then stores.
// Streaming hints: zero reuse in this kernel.
// ---------------------------------------------------------------------------
__global__ __launch_bounds__(TPB) void se_scale_kernel(
    const float* __restrict__ x,
    float* __restrict__ out)
{
    const int plane = blockIdx.x;
    const float g = __ldg(&g_gate[plane]);

    const float4* p = reinterpret_cast<const float4*>(x   + (size_t)plane * HW);
    float4*       q = reinterpret_cast<float4*>(out       + (size_t)plane * HW);

    float4 v[VPT];
    #pragma unroll
    for (int i = 0; i < VPT; i++)
        v[i] = __ldcs(&p[threadIdx.x + i * TPB]);

    #pragma unroll
    for (int i = 0; i < VPT; i++) {
        v[i].x *= g; v[i].y *= g; v[i].z *= g; v[i].w *= g;
        __stcs(&q[threadIdx.x + i * TPB], v[i]);
    }
}

// ---------------------------------------------------------------------------
extern "C" void kernel_launch(void* const* d_in, const int* in_sizes, int n_in,
                              void* d_out, int out_size)
{
    const float* x        = (const float*)d_in[0];
    const float* w_reduce = (const float*)d_in[1];
    const float* b_reduce = (const float*)d_in[2];
    const float* w_expand = (const float*)d_in[3];
    const float* b_expand = (const float*)d_in[4];
    float* out = (float*)d_out;

    se_pool_kernel<<<PLANES, TPB>>>(x);
    se_mlp_kernel<<<N_BATCH, 256>>>(w_reduce, b_reduce, w_expand, b_expand);
    se_scale_kernel<<<PLANES, TPB>>>(x, out);
}

// round 4
// speedup vs baseline: 1.0406x; 1.0057x over previous
#include <cuda_runtime.h>
#include <math.h>

#define N_BATCH 32
#define C_IN    256
#define C_SQ    64
#define HW      12544              // 112*112
#define HW4     3136               // HW/4 float4 per plane
#define PLANES  (N_BATCH * C_IN)   // 8192
#define TPB     448                // 448 * 7 == 3136 exactly
#define VPT     7                  // float4 per thread (scale kernel)

// Scratch (no allocations allowed)
__device__ float g_pool[PLANES];
__device__ float g_gate[PLANES];

// ---------------------------------------------------------------------------
// Kernel 1: global average pool. One block per (n,c) plane, 256 threads,
// strided float4 loop, DEFAULT cache policy (leave the tail resident in L2
// for the scale kernel's reversed read order).
// ---------------------------------------------------------------------------
__global__ __launch_bounds__(256) void se_pool_kernel(
    const float* __restrict__ x)
{
    const int plane = blockIdx.x;
    const float4* p = reinterpret_cast<const float4*>(x + (size_t)plane * HW);

    float sum = 0.0f;
    #pragma unroll 4
    for (int i = threadIdx.x; i < HW4; i += 256) {
        float4 v = p[i];
        sum += (v.x + v.y) + (v.z + v.w);
    }

    // warp reduce
    #pragma unroll
    for (int off = 16; off > 0; off >>= 1)
        sum += __shfl_down_sync(0xFFFFFFFFu, sum, off);

    __shared__ float warp_sums[8];
    const int lane = threadIdx.x & 31;
    const int wid  = threadIdx.x >> 5;
    if (lane == 0) warp_sums[wid] = sum;
    __syncthreads();

    if (wid == 0) {
        float s = (lane < 8) ? warp_sums[lane] : 0.0f;
        #pragma unroll
        for (int off = 4; off > 0; off >>= 1)
            s += __shfl_down_sync(0xFFFFFFFFu, s, off);
        if (lane == 0)
            g_pool[plane] = s * (1.0f / (float)HW);
    }
}

// ---------------------------------------------------------------------------
// Kernel 2: MLP  s -> relu(W_r s + b_r) -> sigmoid(W_e . + b_e) -> gate
// One block per batch element, 256 threads (one per output channel).
// ---------------------------------------------------------------------------
__global__ __launch_bounds__(256) void se_mlp_kernel(
    const float* __restrict__ w_reduce,   // [C_SQ, C_IN]
    const float* __restrict__ b_reduce,   // [C_SQ]
    const float* __restrict__ w_expand,   // [C_IN, C_SQ]
    const float* __restrict__ b_expand)   // [C_IN]
{
    const int n   = blockIdx.x;
    const int tid = threadIdx.x;

    __shared__ float s_in[C_IN];
    __shared__ float s_red[C_SQ];

    s_in[tid] = g_pool[n * C_IN + tid];
    __syncthreads();

    if (tid < C_SQ) {
        float acc = b_reduce[tid];
        const float* wr = w_reduce + tid * C_IN;
        #pragma unroll 8
        for (int c = 0; c < C_IN; c++)
            acc = fmaf(wr[c], s_in[c], acc);
        s_red[tid] = fmaxf(acc, 0.0f);
    }
    __syncthreads();

    float acc = b_expand[tid];
    const float* we = w_expand + tid * C_SQ;
    #pragma unroll 8
    for (int k = 0; k < C_SQ; k++)
        acc = fmaf(we[k], s_red[k], acc);

    g_gate[n * C_IN + tid] = 1.0f / (1.0f + __expf(-acc));
}

// ---------------------------------------------------------------------------
// Kernel 3: out = gate[plane] * x. One block per plane, REVERSED plane order
// so the first blocks read the planes the pool kernel read last (still L2-
// resident). 448 threads x 7 float4, loads front-batched (default cache to
// exploit L2 hits), streaming stores.
// ---------------------------------------------------------------------------
__global__ __launch_bounds__(TPB) void se_scale_kernel(
    const float* __restrict__ x,
    float* __restrict__ out)
{
    const int plane = (PLANES - 1) - blockIdx.x;   // reverse order for L2 reuse
    const float g = __ldg(&g_gate[plane]);

    const float4* p = reinterpret_cast<const float4*>(x   + (size_t)plane * HW);
    float4*       q = reinterpret_cast<float4*>(out       + (size_t)plane * HW);

    float4 v[VPT];
    #pragma unroll
    for (int i = 0; i < VPT; i++)
        v[i] = p[threadIdx.x + i * TPB];

    #pragma unroll
    for (int i = 0; i < VPT; i++) {
        v[i].x *= g; v[i].y *= g; v[i].z *= g; v[i].w *= g;
        __stcs(&q[threadIdx.x + i * TPB], v[i]);
    }
}

// ---------------------------------------------------------------------------
extern "C" void kernel_launch(void* const* d_in, const int* in_sizes, int n_in,
                              void* d_out, int out_size)
{
    const float* x        = (const float*)d_in[0];
    const float* w_reduce = (const float*)d_in[1];
    const float* b_reduce = (const float*)d_in[2];
    const float* w_expand = (const float*)d_in[3];
    const float* b_expand = (const float*)d_in[4];
    float* out = (float*)d_out;

    se_pool_kernel<<<PLANES, 256>>>(x);
    se_mlp_kernel<<<N_BATCH, 256>>>(w_reduce, b_reduce, w_expand, b_expand);
    se_scale_kernel<<<PLANES, TPB>>>(x, out);
}